// round 8
// baseline (speedup 1.0000x reference)
#include <cuda_runtime.h>
#include <math_constants.h>

// Problem shape (fixed by the dataset)
#define NB 4
#define NQ 2048
#define NR 16384
#define DIM 64
#define KK 16
#define KC 20                   // candidates kept per split (margin over KK)
#define NSPLIT 4
#define QPB 128                 // queries per block == threads per block
#define TR 128                  // refs per smem tile
#define RPS (NR / NSPLIT)       // 4096 refs per split
#define NCAND (NSPLIT * KC)     // 80 candidates per query

// Scratch (device globals: harness forbids cudaMalloc)
__device__ float g_r2[NB * NR];
__device__ int   g_cand[(size_t)NB * NQ * NCAND];

// ---------------------------------------------------------------------------
// XLA-GPU row-reduction emulation for sum(x*x) over 64 elements:
// warp-per-row, lane l accumulates x[l], x[l+32] (strided), then shfl_down
// tree with offsets 16,8,4,2,1. Emulated serially with identical rounding.
// ---------------------------------------------------------------------------
__device__ __forceinline__ float xla_row_sumsq(const float* __restrict__ x) {
    float a[32];
#pragma unroll
    for (int l = 0; l < 32; ++l)
        a[l] = __fadd_rn(__fmul_rn(x[l], x[l]),
                         __fmul_rn(x[l + 32], x[l + 32]));
#pragma unroll
    for (int off = 16; off >= 1; off >>= 1) {
#pragma unroll
        for (int l = 0; l < 16; ++l)
            if (l < off)
                a[l] = __fadd_rn(a[l], a[l + off]);
    }
    return a[0];
}

// ---------------------------------------------------------------------------
// Kernel 0: ref squared norms (fp32, used only for pass-1 candidate ranking;
// accuracy here only affects which candidates are kept, not final ordering).
// ---------------------------------------------------------------------------
__global__ void r2_kernel(const float* __restrict__ ref) {
    int i = blockIdx.x * blockDim.x + threadIdx.x;
    if (i >= NB * NR) return;
    const float4* p = reinterpret_cast<const float4*>(ref + (size_t)i * DIM);
    float s = 0.f;
#pragma unroll
    for (int j = 0; j < DIM / 4; ++j) {
        float4 v = p[j];
        s += v.x * v.x + v.y * v.y + v.z * v.z + v.w * v.w;
    }
    g_r2[i] = s;
}

// ---------------------------------------------------------------------------
// Kernel 1: candidate generation. Grid (NQ/QPB, NSPLIT, NB), 128 threads.
// Each thread owns one query, streams its ref split through smem tiles,
// maintains a top-20 of s = r2 - 2*dot in registers. This ranking is only a
// candidate filter; exact reference-emulated ordering happens in kernel 2.
// ---------------------------------------------------------------------------
__global__ __launch_bounds__(QPB)
void knn_partial(const float* __restrict__ ref, const float* __restrict__ query) {
    __shared__ float4 s_ref[TR * DIM / 4];   // 32 KB
    __shared__ float  s_r2[TR];

    const int b     = blockIdx.z;
    const int split = blockIdx.y;
    const int qc    = blockIdx.x;
    const int tid   = threadIdx.x;
    const int q     = qc * QPB + tid;

    // Load query, pre-scale by -2 so inner loop is pure FMA.
    const float4* qp = reinterpret_cast<const float4*>(query + ((size_t)b * NQ + q) * DIM);
    float nq[DIM];
#pragma unroll
    for (int j = 0; j < DIM / 4; ++j) {
        float4 v = qp[j];
        nq[4 * j + 0] = -2.f * v.x;
        nq[4 * j + 1] = -2.f * v.y;
        nq[4 * j + 2] = -2.f * v.z;
        nq[4 * j + 3] = -2.f * v.w;
    }

    float dk[KC];
    int   ik[KC];
#pragma unroll
    for (int j = 0; j < KC; ++j) { dk[j] = CUDART_INF_F; ik[j] = 0; }

    const float4* refb = reinterpret_cast<const float4*>(ref + (size_t)b * NR * DIM);
    const float*  r2b  = g_r2 + b * NR;
    const int     base0 = split * RPS;

    for (int t = 0; t < RPS / TR; ++t) {
        const int rbase = base0 + t * TR;
        // Cooperative, fully-coalesced tile load: 2048 float4s, 16 per thread.
#pragma unroll
        for (int j = 0; j < (TR * DIM / 4) / QPB; ++j)
            s_ref[j * QPB + tid] = refb[(size_t)rbase * (DIM / 4) + j * QPB + tid];
        s_r2[tid] = r2b[rbase + tid];    // TR == QPB
        __syncthreads();

        for (int r = 0; r < TR; ++r) {
            const float4* rp = &s_ref[r * (DIM / 4)];
            float a0 = s_r2[r], a1 = 0.f, a2 = 0.f, a3 = 0.f;
#pragma unroll
            for (int j = 0; j < DIM / 4; ++j) {
                float4 v = rp[j];                 // broadcast LDS.128, conflict-free
                a0 = fmaf(nq[4 * j + 0], v.x, a0);
                a1 = fmaf(nq[4 * j + 1], v.y, a1);
                a2 = fmaf(nq[4 * j + 2], v.z, a2);
                a3 = fmaf(nq[4 * j + 3], v.w, a3);
            }
            float s = (a0 + a1) + (a2 + a3);
            if (s < dk[KC - 1]) {                 // rare (~1% of refs per lane)
                const int rg = rbase + r;
#pragma unroll
                for (int j = KC - 1; j >= 0; --j) {
                    float prev = (j > 0) ? dk[j - 1] : -CUDART_INF_F;
                    if (s < prev)           { dk[j] = dk[j - 1]; ik[j] = ik[j - 1]; }
                    else if (s < dk[j])     { dk[j] = s;         ik[j] = rg;        }
                }
            }
        }
        __syncthreads();
    }

    const size_t o = (((size_t)b * NQ + q) * NSPLIT + split) * KC;
#pragma unroll
    for (int j = 0; j < KC; ++j) g_cand[o + j] = ik[j];
}

// ---------------------------------------------------------------------------
// Kernel 2: BIT-EXACT reference emulation + final select. One thread/query.
// Reference model (XLA on GPU):
//   dot   = cuBLAS SGEMM: single sequential fused-FMA chain, k ascending
//   r2,q2 = XLA warp row-reduction: strided lane accum + shfl tree (emulated)
//   key   = max( fl( fl(q2+r2) - fl(2*dot) ), 0 )
// Select 16 by lexicographic (key, idx) == top_k's stable tie-break.
// Output D = sqrtf(key), I as f32 values (single output dtype buffer).
// ---------------------------------------------------------------------------
__global__ void knn_rerank(const float* __restrict__ ref,
                           const float* __restrict__ query,
                           float* __restrict__ outD, float* __restrict__ outI) {
    int gq = blockIdx.x * blockDim.x + threadIdx.x;
    if (gq >= NB * NQ) return;
    const int b = gq / NQ;

    // Query in registers + XLA-emulated q2.
    const float4* qp = reinterpret_cast<const float4*>(query + (size_t)gq * DIM);
    float qv[DIM];
#pragma unroll
    for (int j = 0; j < DIM / 4; ++j) {
        float4 v = qp[j];
        qv[4 * j + 0] = v.x; qv[4 * j + 1] = v.y;
        qv[4 * j + 2] = v.z; qv[4 * j + 3] = v.w;
    }
    const float q2f = xla_row_sumsq(qv);

    float dk[KK];
    int   ik[KK];
#pragma unroll
    for (int j = 0; j < KK; ++j) { dk[j] = CUDART_INF_F; ik[j] = 0x7FFFFFFF; }

    const int* cand = g_cand + (size_t)gq * NCAND;
    const float4* refb = reinterpret_cast<const float4*>(ref + (size_t)b * NR * DIM);

    for (int c = 0; c < NCAND; ++c) {
        const int idx = cand[c];
        const float4* rp = refb + (size_t)idx * (DIM / 4);
        float rv[DIM];
#pragma unroll
        for (int j = 0; j < DIM / 4; ++j) {
            float4 v = rp[j];
            rv[4 * j + 0] = v.x; rv[4 * j + 1] = v.y;
            rv[4 * j + 2] = v.z; rv[4 * j + 3] = v.w;
        }
        // cuBLAS-style dot: single sequential FMA chain, k ascending.
        float dotf = 0.f;
#pragma unroll
        for (int k = 0; k < DIM; ++k)
            dotf = fmaf(qv[k], rv[k], dotf);
        // XLA warp-tree r2.
        const float r2f = xla_row_sumsq(rv);

        const float s12 = __fadd_rn(q2f, r2f);          // q2 + r2
        const float t2d = __fmul_rn(2.0f, dotf);        // 2*dot (exact)
        const float key = fmaxf(__fadd_rn(s12, -t2d), 0.f);

        // lexicographic (key, idx) insertion; matches stable top_k
        bool better_last = (key < dk[KK - 1]) ||
                           (key == dk[KK - 1] && idx < ik[KK - 1]);
        if (better_last) {
#pragma unroll
            for (int j = KK - 1; j >= 0; --j) {
                bool lt_prev = (j > 0) &&
                    ((key < dk[j - 1]) || (key == dk[j - 1] && idx < ik[j - 1]));
                bool lt_here = (key < dk[j]) || (key == dk[j] && idx < ik[j]);
                if (lt_prev)      { dk[j] = dk[j - 1]; ik[j] = ik[j - 1]; }
                else if (lt_here) { dk[j] = key;       ik[j] = idx;       }
            }
        }
    }

#pragma unroll
    for (int j = 0; j < KK; ++j) {
        outD[(size_t)gq * KK + j] = sqrtf(dk[j]);
        outI[(size_t)gq * KK + j] = (float)ik[j];
    }
}

// ---------------------------------------------------------------------------
// Launch: ref = d_in[0], query = d_in[1] (setup_inputs order).
// d_out layout: D [NB*NQ*KK] f32, then I [NB*NQ*KK] f32 (single output dtype).
// ---------------------------------------------------------------------------
extern "C" void kernel_launch(void* const* d_in, const int* in_sizes, int n_in,
                              void* d_out, int out_size) {
    const float* ref   = (const float*)d_in[0];
    const float* query = (const float*)d_in[1];

    float* outD = (float*)d_out;
    float* outI = (float*)d_out + (size_t)NB * NQ * KK;

    r2_kernel<<<(NB * NR + 255) / 256, 256>>>(ref);
    knn_partial<<<dim3(NQ / QPB, NSPLIT, NB), QPB>>>(ref, query);
    knn_rerank<<<(NB * NQ + 63) / 64, 64>>>(ref, query, outD, outI);
}

// round 9
// speedup vs baseline: 2.2721x; 2.2721x over previous
#include <cuda_runtime.h>
#include <math_constants.h>

// Problem shape (fixed by the dataset)
#define NB 4
#define NQ 2048
#define NR 16384
#define DIM 64
#define KK 16
#define KC 20                   // candidates kept per split (margin over KK)
#define NSPLIT 4
#define QPB 128                 // queries per block == threads per block
#define TR 128                  // refs per smem tile
#define RPS (NR / NSPLIT)       // 4096 refs per split
#define NTILE (RPS / TR)        // 32 tiles per split
#define NCAND (NSPLIT * KC)     // 80 candidates per query

// Scratch (device globals: harness forbids cudaMalloc)
__device__ float g_r2[NB * NR];
__device__ int   g_cand[(size_t)NB * NQ * NCAND];

// ---------------------------------------------------------------------------
// Packed f32x2 helpers (Blackwell FFMA2 path — only reachable via PTX)
// ---------------------------------------------------------------------------
__device__ __forceinline__ unsigned long long pk2(float lo, float hi) {
    unsigned long long p;
    asm("mov.b64 %0, {%1, %2};" : "=l"(p) : "f"(lo), "f"(hi));
    return p;
}
__device__ __forceinline__ void upk2(float& lo, float& hi, unsigned long long p) {
    asm("mov.b64 {%0, %1}, %2;" : "=f"(lo), "=f"(hi) : "l"(p));
}
__device__ __forceinline__ unsigned long long ffma2(unsigned long long a,
                                                    unsigned long long b,
                                                    unsigned long long c) {
    unsigned long long d;
    asm("fma.rn.f32x2 %0, %1, %2, %3;" : "=l"(d) : "l"(a), "l"(b), "l"(c));
    return d;
}
__device__ __forceinline__ unsigned long long fadd2(unsigned long long a,
                                                    unsigned long long b) {
    unsigned long long d;
    asm("add.rn.f32x2 %0, %1, %2;" : "=l"(d) : "l"(a), "l"(b));
    return d;
}

// cp.async helpers
__device__ __forceinline__ void cp16(unsigned int dst, const void* src) {
    asm volatile("cp.async.cg.shared.global [%0], [%1], 16;" :: "r"(dst), "l"(src));
}
__device__ __forceinline__ void cp4(unsigned int dst, const void* src) {
    asm volatile("cp.async.ca.shared.global [%0], [%1], 4;" :: "r"(dst), "l"(src));
}
__device__ __forceinline__ void cp_commit() { asm volatile("cp.async.commit_group;"); }
__device__ __forceinline__ void cp_waitall() { asm volatile("cp.async.wait_group 0;" ::: "memory"); }

// ---------------------------------------------------------------------------
// XLA-GPU row-reduction emulation for sum(x*x) over 64 elements (verified
// bit-exact vs reference in R8): strided lane accum + shfl_down tree.
// ---------------------------------------------------------------------------
__device__ __forceinline__ float xla_row_sumsq(const float* __restrict__ x) {
    float a[32];
#pragma unroll
    for (int l = 0; l < 32; ++l)
        a[l] = __fadd_rn(__fmul_rn(x[l], x[l]),
                         __fmul_rn(x[l + 32], x[l + 32]));
#pragma unroll
    for (int off = 16; off >= 1; off >>= 1) {
#pragma unroll
        for (int l = 0; l < 16; ++l)
            if (l < off)
                a[l] = __fadd_rn(a[l], a[l + off]);
    }
    return a[0];
}

// ---------------------------------------------------------------------------
// Kernel 0: ref squared norms (fp32, pass-1 filter only).
// ---------------------------------------------------------------------------
__global__ void r2_kernel(const float* __restrict__ ref) {
    int i = blockIdx.x * blockDim.x + threadIdx.x;
    if (i >= NB * NR) return;
    const float4* p = reinterpret_cast<const float4*>(ref + (size_t)i * DIM);
    float s = 0.f;
#pragma unroll
    for (int j = 0; j < DIM / 4; ++j) {
        float4 v = p[j];
        s += v.x * v.x + v.y * v.y + v.z * v.z + v.w * v.w;
    }
    g_r2[i] = s;
}

// ---------------------------------------------------------------------------
// Kernel 1: candidate generation. Grid (NQ/QPB, NSPLIT, NB), 128 threads.
// Thread-per-query; refs stream through a double-buffered smem tile ring
// (cp.async). Distance inner loop uses packed f32x2 FMA (32 FFMA2 per ref).
// Selection: UNORDERED top-KC via smem max-replace buffer (the rerank kernel
// consumes a candidate SET; order is irrelevant).
// ---------------------------------------------------------------------------
__global__ __launch_bounds__(QPB)
void knn_partial(const float* __restrict__ ref, const float* __restrict__ query) {
    __shared__ ulonglong2      s_ref[2][TR * 16];   // 2 x 32 KB (64 f32 per row)
    __shared__ float           s_r2s[2][TR];
    __shared__ float           s_val[KC][QPB];      // 10 KB
    __shared__ unsigned short  s_idx[KC][QPB];      // 5 KB

    const int b     = blockIdx.z;
    const int split = blockIdx.y;
    const int qc    = blockIdx.x;
    const int tid   = threadIdx.x;
    const int q     = qc * QPB + tid;

    // Query packed as 32 f32x2 pairs, pre-scaled by -2.
    const float4* qp = reinterpret_cast<const float4*>(query + ((size_t)b * NQ + q) * DIM);
    unsigned long long nq2[32];
#pragma unroll
    for (int j = 0; j < DIM / 4; ++j) {
        float4 v = qp[j];
        nq2[2 * j + 0] = pk2(-2.f * v.x, -2.f * v.y);
        nq2[2 * j + 1] = pk2(-2.f * v.z, -2.f * v.w);
    }

    // Init selection buffers.
#pragma unroll
    for (int j = 0; j < KC; ++j) { s_val[j][tid] = CUDART_INF_F; s_idx[j][tid] = 0; }
    float mval = CUDART_INF_F;
    int   mslot = 0;

    const ulonglong2* refb =
        reinterpret_cast<const ulonglong2*>(ref + (size_t)b * NR * DIM);
    const float* r2b  = g_r2 + b * NR;
    const int    base0 = split * RPS;

    // Prologue: async-load tile 0.
    {
        const int rbase = base0;
#pragma unroll
        for (int j = 0; j < 16; ++j)
            cp16((unsigned int)__cvta_generic_to_shared(&s_ref[0][j * QPB + tid]),
                 refb + (size_t)rbase * 16 + j * QPB + tid);
        cp4((unsigned int)__cvta_generic_to_shared(&s_r2s[0][tid]), r2b + rbase + tid);
        cp_commit();
        cp_waitall();
    }
    __syncthreads();

    for (int t = 0; t < NTILE; ++t) {
        const int buf   = t & 1;
        const int rbase = base0 + t * TR;

        // Prefetch next tile into the other buffer (overlaps with compute).
        if (t + 1 < NTILE) {
            const int nb_ = (t + 1) & 1;
            const int nbase = base0 + (t + 1) * TR;
#pragma unroll
            for (int j = 0; j < 16; ++j)
                cp16((unsigned int)__cvta_generic_to_shared(&s_ref[nb_][j * QPB + tid]),
                     refb + (size_t)nbase * 16 + j * QPB + tid);
            cp4((unsigned int)__cvta_generic_to_shared(&s_r2s[nb_][tid]), r2b + nbase + tid);
            cp_commit();
        }

        for (int r = 0; r < TR; ++r) {
            const ulonglong2* rp = &s_ref[buf][r * 16];
            unsigned long long a0 = pk2(s_r2s[buf][r], 0.f);
            unsigned long long a1 = 0, a2 = 0, a3 = 0;   // +0.0 packed
#pragma unroll
            for (int j = 0; j < 8; ++j) {
                ulonglong2 v0 = rp[2 * j];
                ulonglong2 v1 = rp[2 * j + 1];
                a0 = ffma2(nq2[4 * j + 0], v0.x, a0);
                a1 = ffma2(nq2[4 * j + 1], v0.y, a1);
                a2 = ffma2(nq2[4 * j + 2], v1.x, a2);
                a3 = ffma2(nq2[4 * j + 3], v1.y, a3);
            }
            unsigned long long p = fadd2(fadd2(a0, a1), fadd2(a2, a3));
            float lo, hi; upk2(lo, hi, p);
            float s = lo + hi;

            if (s < mval) {                       // replace current worst
                s_val[mslot][tid] = s;
                s_idx[mslot][tid] = (unsigned short)(rbase + r);
                // rescan for new max
                float nm = -CUDART_INF_F; int ns = 0;
#pragma unroll
                for (int j = 0; j < KC; ++j) {
                    float v = s_val[j][tid];
                    if (v > nm) { nm = v; ns = j; }
                }
                mval = nm; mslot = ns;
            }
        }

        cp_waitall();
        __syncthreads();
    }

    const size_t o = (((size_t)b * NQ + q) * NSPLIT + split) * KC;
#pragma unroll
    for (int j = 0; j < KC; ++j) g_cand[o + j] = (int)s_idx[j][tid];
}

// ---------------------------------------------------------------------------
// Kernel 2: BIT-EXACT reference emulation + final select (VERIFIED in R8).
//   dot   = single sequential fused-FMA chain, k ascending (cuBLAS SGEMM)
//   r2,q2 = XLA warp row-reduction (strided lane accum + shfl tree)
//   key   = max( fl( fl(q2+r2) - fl(2*dot) ), 0 )
// Select 16 by lexicographic (key, idx) == top_k's stable tie-break.
// Candidate order in g_cand is irrelevant (pure set).
// ---------------------------------------------------------------------------
__global__ void knn_rerank(const float* __restrict__ ref,
                           const float* __restrict__ query,
                           float* __restrict__ outD, float* __restrict__ outI) {
    int gq = blockIdx.x * blockDim.x + threadIdx.x;
    if (gq >= NB * NQ) return;
    const int b = gq / NQ;

    const float4* qp = reinterpret_cast<const float4*>(query + (size_t)gq * DIM);
    float qv[DIM];
#pragma unroll
    for (int j = 0; j < DIM / 4; ++j) {
        float4 v = qp[j];
        qv[4 * j + 0] = v.x; qv[4 * j + 1] = v.y;
        qv[4 * j + 2] = v.z; qv[4 * j + 3] = v.w;
    }
    const float q2f = xla_row_sumsq(qv);

    float dk[KK];
    int   ik[KK];
#pragma unroll
    for (int j = 0; j < KK; ++j) { dk[j] = CUDART_INF_F; ik[j] = 0x7FFFFFFF; }

    const int* cand = g_cand + (size_t)gq * NCAND;
    const float4* refb = reinterpret_cast<const float4*>(ref + (size_t)b * NR * DIM);

    for (int c = 0; c < NCAND; ++c) {
        const int idx = cand[c];
        const float4* rp = refb + (size_t)idx * (DIM / 4);
        float rv[DIM];
#pragma unroll
        for (int j = 0; j < DIM / 4; ++j) {
            float4 v = rp[j];
            rv[4 * j + 0] = v.x; rv[4 * j + 1] = v.y;
            rv[4 * j + 2] = v.z; rv[4 * j + 3] = v.w;
        }
        float dotf = 0.f;
#pragma unroll
        for (int k = 0; k < DIM; ++k)
            dotf = fmaf(qv[k], rv[k], dotf);
        const float r2f = xla_row_sumsq(rv);

        const float s12 = __fadd_rn(q2f, r2f);
        const float t2d = __fmul_rn(2.0f, dotf);
        const float key = fmaxf(__fadd_rn(s12, -t2d), 0.f);

        bool better_last = (key < dk[KK - 1]) ||
                           (key == dk[KK - 1] && idx < ik[KK - 1]);
        if (better_last) {
#pragma unroll
            for (int j = KK - 1; j >= 0; --j) {
                bool lt_prev = (j > 0) &&
                    ((key < dk[j - 1]) || (key == dk[j - 1] && idx < ik[j - 1]));
                bool lt_here = (key < dk[j]) || (key == dk[j] && idx < ik[j]);
                if (lt_prev)      { dk[j] = dk[j - 1]; ik[j] = ik[j - 1]; }
                else if (lt_here) { dk[j] = key;       ik[j] = idx;       }
            }
        }
    }

#pragma unroll
    for (int j = 0; j < KK; ++j) {
        outD[(size_t)gq * KK + j] = sqrtf(dk[j]);
        outI[(size_t)gq * KK + j] = (float)ik[j];
    }
}

// ---------------------------------------------------------------------------
// Launch: ref = d_in[0], query = d_in[1].
// d_out layout: D [NB*NQ*KK] f32, then I [NB*NQ*KK] f32 (single output dtype).
// ---------------------------------------------------------------------------
extern "C" void kernel_launch(void* const* d_in, const int* in_sizes, int n_in,
                              void* d_out, int out_size) {
    const float* ref   = (const float*)d_in[0];
    const float* query = (const float*)d_in[1];

    float* outD = (float*)d_out;
    float* outI = (float*)d_out + (size_t)NB * NQ * KK;

    r2_kernel<<<(NB * NR + 255) / 256, 256>>>(ref);
    knn_partial<<<dim3(NQ / QPB, NSPLIT, NB), QPB>>>(ref, query);
    knn_rerank<<<(NB * NQ + 63) / 64, 64>>>(ref, query, outD, outI);
}